// round 1
// baseline (speedup 1.0000x reference)
#include <cuda_runtime.h>

#define B_ 8
#define C_ 12
#define S_ 784
#define N_ 785
#define D_ 768
#define H_ 28
#define PATCHNUM 84
#define K_ 512
#define SCALE_ 0.7f

// ---------------- scratch (static, no allocs) ----------------
__device__ float          g_new[B_*C_*S_];     // new_score
__device__ unsigned char  g_sel[B_*C_*S_];     // select mask
__device__ float          g_u[B_*K_];          // Ppos*relu(v1)+Pneg*min(v1,0)
__device__ float          g_pa[B_];            // pw[anchor]
__device__ __align__(16) float g_structA[B_*D_];
__device__ int            g_key[B_*S_];        // (count<<10)|(1023-s)
__device__ int            g_patch[B_*64];      // top-sn rows (+1)

// ---------------- Kernel A: per-(b,c) top-84 select via exact rank ----------------
// grid (96, 4) x 256 : each block loads the 784-score row, ranks 196 of them.
__global__ void kA(const float* __restrict__ x) {
    int bc = blockIdx.x;          // b*C + c
    int part = blockIdx.y;        // 0..3
    __shared__ float sc[S_];
    const float* px = x + (size_t)bc * N_ * N_ + 1;   // x[b,c,0,1:]
    for (int s = threadIdx.x; s < S_; s += 256) sc[s] = px[s];
    __syncthreads();
    if (threadIdx.x < 196) {
        int s = part * 196 + threadIdx.x;
        float v = sc[s];
        int rank = 0;
        #pragma unroll 4
        for (int j = 0; j < S_; j++) {
            float w = sc[j];
            // strict-greater, or equal with smaller index (lax.top_k tie order)
            rank += (w > v || (w == v && j < s)) ? 1 : 0;
        }
        bool sel = (rank < PATCHNUM);
        g_new[bc*S_ + s] = sel ? v : SCALE_ * v;
        g_sel[bc*S_ + s] = sel ? 1 : 0;
    }
}

// ---------------- Kernel B: per-batch stats ----------------
// grid 8 x 256 : m, mean, binary, anchor argmax, c_d/c_a/Ppos/Pneg, u, conv->keys
__global__ void kB(const float* __restrict__ w1) {
    int b = blockIdx.x;
    int tid = threadIdx.x;
    __shared__ float sm[S_];     // m[s] = sum_c new_score
    __shared__ float scnt[S_];   // count[s] pre-conv
    __shared__ float red[256];
    __shared__ int   redi[256];
    __shared__ float sres[4];

    for (int s = tid; s < S_; s += 256) {
        float acc = 0.0f; int cn = 0;
        #pragma unroll
        for (int c = 0; c < C_; c++) {
            acc += g_new[(b*C_ + c)*S_ + s];
            cn  += g_sel[(b*C_ + c)*S_ + s];
        }
        sm[s] = acc;
        scnt[s] = (float)cn;
    }
    __syncthreads();

    // mean of m
    float p = 0.0f;
    for (int s = tid; s < S_; s += 256) p += sm[s];
    red[tid] = p; __syncthreads();
    for (int o = 128; o > 0; o >>= 1) { if (tid < o) red[tid] += red[tid+o]; __syncthreads(); }
    float mean = red[0] * (1.0f / (float)S_);
    __syncthreads();

    // argmax of binary*pw (first-index ties)
    float bv = -1e30f; int bi = S_;
    for (int s = tid; s < S_; s += 256) {
        float pw = sm[s] * (1.0f/12.0f);
        float v  = (sm[s] > mean) ? pw : 0.0f;
        if (v > bv || (v == bv && s < bi)) { bv = v; bi = s; }
    }
    red[tid] = bv; redi[tid] = bi; __syncthreads();
    for (int o = 128; o > 0; o >>= 1) {
        if (tid < o) {
            float v2 = red[tid+o]; int i2 = redi[tid+o];
            if (v2 > red[tid] || (v2 == red[tid] && i2 < redi[tid])) { red[tid] = v2; redi[tid] = i2; }
        }
        __syncthreads();
    }
    int anchor = redi[0];
    __syncthreads();

    // scalar sums: c_d, c_a, Ppos, Pneg
    int ai = anchor / H_, aj = anchor % H_;
    const float INVPI = 0.318309886183790672f;
    float cd = 0.0f, ca = 0.0f, pp = 0.0f, pn = 0.0f;
    for (int s = tid; s < S_; s += 256) {
        float pw = sm[s] * (1.0f/12.0f);
        int ii = s / H_, jj = s % H_;
        float di = (float)(ii - ai) / (float)H_;
        float dj = (float)(jj - aj) / (float)H_;
        float dist = sqrtf(di*di + dj*dj);
        float ang  = (atan2f(dj, di) * INVPI + 1.0f) * 0.5f;
        cd += pw * dist;
        ca += pw * ang;
        float q = pw * pw;
        if (pw > 0.0f) pp += q; else if (pw < 0.0f) pn += q;
    }
    float vals[4] = {cd, ca, pp, pn};
    for (int r4 = 0; r4 < 4; r4++) {
        red[tid] = vals[r4]; __syncthreads();
        for (int o = 128; o > 0; o >>= 1) { if (tid < o) red[tid] += red[tid+o]; __syncthreads(); }
        if (tid == 0) sres[r4] = red[0];
        __syncthreads();
    }
    float CD = sres[0], CA = sres[1], PP = sres[2], PN = sres[3];

    // u[k] = Ppos*relu(v1) + Pneg*min(v1,0)
    for (int k = tid; k < K_; k += 256) {
        float v1 = CD * w1[k] + CA * w1[K_ + k];
        g_u[b*K_ + k] = PP * fmaxf(v1, 0.0f) + PN * fminf(v1, 0.0f);
    }
    if (tid == 0) g_pa[b] = sm[anchor] * (1.0f/12.0f);

    // 3x3 conv of counts (weights (2-|di|)*(2-|dj|)), integer keys for stable sort
    for (int s = tid; s < S_; s += 256) {
        int ii = s / H_, jj = s % H_;
        float acc = 0.0f;
        #pragma unroll
        for (int d2 = -1; d2 <= 1; d2++) {
            #pragma unroll
            for (int e2 = -1; e2 <= 1; e2++) {
                int i2 = ii + d2, j2 = jj + e2;
                if (i2 >= 0 && i2 < H_ && j2 >= 0 && j2 < H_) {
                    int wd = 2 - (d2 < 0 ? -d2 : d2);
                    int we = 2 - (e2 < 0 ? -e2 : e2);
                    acc += (float)(wd * we) * scnt[i2*H_ + j2];
                }
            }
        }
        int ic = (int)(acc + 0.5f);          // exact small integer
        g_key[b*S_ + s] = (ic << 10) | (1023 - s);  // desc count, asc index
    }
}

// ---------------- Kernel Rank: top-sn by exact rank ----------------
// grid (8, 4) x 256
__global__ void kRank(int sn) {
    int b = blockIdx.x, part = blockIdx.y;
    __shared__ int sk[S_];
    for (int s = threadIdx.x; s < S_; s += 256) sk[s] = g_key[b*S_ + s];
    __syncthreads();
    if (threadIdx.x < 196) {
        int s = part * 196 + threadIdx.x;
        int k0 = sk[s];
        int rank = 0;
        #pragma unroll 4
        for (int j = 0; j < S_; j++) rank += (sk[j] > k0) ? 1 : 0;
        if (rank < sn) g_patch[b*64 + rank] = s + 1;
    }
}

// ---------------- Kernel MV: struct_anchor[d] = leaky(pa * u@W2[:,d]) ----------------
// grid (12, 8) x 256 : each block 64 d-cols, 4-way k-split
__global__ void kMV(const float* __restrict__ w2) {
    int b = blockIdx.y;
    int d0 = blockIdx.x * 64;
    int tid = threadIdx.x;
    int kg = tid >> 6, dl = tid & 63;
    __shared__ float su[K_];
    __shared__ float part[256];
    for (int k = tid; k < K_; k += 256) su[k] = g_u[b*K_ + k];
    __syncthreads();
    float acc = 0.0f;
    int kbase = kg * 128;
    #pragma unroll 8
    for (int kk = 0; kk < 128; kk++) {
        int k = kbase + kk;
        acc += su[k] * w2[k*D_ + d0 + dl];
    }
    part[tid] = acc;
    __syncthreads();
    if (kg == 0) {
        float s = part[dl] + part[64+dl] + part[128+dl] + part[192+dl];
        float o = g_pa[b] * s;
        g_structA[b*D_ + d0 + dl] = (o > 0.0f) ? o : 0.2f * o;
    }
}

// ---------------- Kernel Copy: hs = hidden (+ structA on row 0) ----------------
__global__ void kCopy(const float4* __restrict__ hid, float4* __restrict__ out) {
    int idx = blockIdx.x * 256 + threadIdx.x;
    const int total = B_*N_*D_/4;
    if (idx >= total) return;
    float4 v = hid[idx];
    int f = idx * 4;
    int d = f % D_;
    int r = f / D_;
    int n = r % N_;
    if (n == 0) {
        int b = r / N_;
        const float4 sv = *(const float4*)&g_structA[b*D_ + d];
        v.x += sv.x; v.y += sv.y; v.z += sv.z; v.w += sv.w;
    }
    out[idx] = v;
}

// ---------------- Kernel Gather: selected rows (all >= 1, untouched) ----------------
__global__ void kGather(const float4* __restrict__ hid, float4* __restrict__ out, int sn) {
    int idx = blockIdx.x * 256 + threadIdx.x;
    int total = B_ * sn * (D_/4);
    if (idx >= total) return;
    int dl = idx % (D_/4);
    int qq = idx / (D_/4);
    int q  = qq % sn;
    int b  = qq / sn;
    int row = g_patch[b*64 + q];
    out[B_*N_*(D_/4) + idx] = hid[(b*N_ + row)*(D_/4) + dl];
}

extern "C" void kernel_launch(void* const* d_in, const int* in_sizes, int n_in,
                              void* d_out, int out_size) {
    const float* hid = (const float*)d_in[0];
    const float* x   = (const float*)d_in[1];
    const float* w1  = (const float*)d_in[2];
    const float* w2  = (const float*)d_in[3];
    // select_num recovered from out_size (avoids device->host sync)
    int sn = (out_size - B_*N_*D_) / (B_*D_);
    if (sn < 0)  sn = 0;
    if (sn > 64) sn = 64;

    kA<<<dim3(B_*C_, 4), 256>>>(x);
    kB<<<B_, 256>>>(w1);
    kRank<<<dim3(B_, 4), 256>>>(sn);
    kMV<<<dim3(D_/64, B_), 256>>>(w2);
    kCopy<<<(B_*N_*D_/4 + 255)/256, 256>>>((const float4*)hid, (float4*)d_out);
    if (sn > 0)
        kGather<<<(B_*sn*(D_/4) + 255)/256, 256>>>((const float4*)hid, (float4*)d_out, sn);
}

// round 3
// speedup vs baseline: 1.2495x; 1.2495x over previous
#include <cuda_runtime.h>

#define B_ 8
#define C_ 12
#define S_ 784
#define N_ 785
#define D_ 768
#define H_ 28
#define PATCHNUM 84
#define K_ 512
#define SCALE_ 0.7f

// ---------------- scratch (static, no allocs) ----------------
__device__ float          g_new[B_*C_*S_];     // new_score
__device__ unsigned char  g_sel[B_*C_*S_];     // select mask
__device__ float          g_u[B_*K_];          // Ppos*relu(v1)+Pneg*min(v1,0)
__device__ float          g_pa[B_];            // pw[anchor]
__device__ __align__(16) float g_structA[B_*D_];
__device__ int            g_key[B_*S_];        // (count<<10)|(1023-s)
__device__ int            g_patch[B_*64];      // top-sn rows (+1)

__device__ __forceinline__ unsigned sortkey(float f) {
    unsigned u = __float_as_uint(f);
    return (u & 0x80000000u) ? ~u : (u | 0x80000000u);
}

// ---------------- Kernel A: per-(b,c) top-84 select via radix select ----------------
// grid 96 x 256
__global__ void kA(const float* __restrict__ x) {
    int bc = blockIdx.x, tid = threadIdx.x;
    __shared__ float sc[S_];
    __shared__ unsigned key[S_];
    __shared__ int hist[256];
    __shared__ unsigned s_prefix;
    __shared__ int s_kk, s_G;
    const float* px = x + (size_t)bc * N_ * N_ + 1;   // x[b,c,0,1:]
    for (int s = tid; s < S_; s += 256) { float v = px[s]; sc[s] = v; key[s] = sortkey(v); }
    if (tid == 0) { s_prefix = 0u; s_kk = PATCHNUM; s_G = 0; }
    __syncthreads();

    // 4 rounds of 8-bit radix select for the 84th-largest key
    for (int round = 0; round < 4; round++) {
        int shift = 24 - round * 8;
        hist[tid] = 0;
        __syncthreads();
        unsigned pref = s_prefix; int kk = s_kk;
        for (int s = tid; s < S_; s += 256) {
            unsigned ky = key[s];
            if (round == 0 || (ky >> (shift + 8)) == (pref >> (shift + 8)))
                atomicAdd(&hist[(ky >> shift) & 255], 1);
        }
        __syncthreads();
        if (tid < 32) {
            int base = tid * 8, g = 0;
            #pragma unroll
            for (int i = 0; i < 8; i++) g += hist[base + i];
            int a = g;
            #pragma unroll
            for (int o = 1; o < 32; o <<= 1) { int t = __shfl_down_sync(0xffffffffu, a, o); if (tid + o < 32) a += t; }
            int above = a - g;   // keys with digit in strictly-higher 8-bin groups
            if (above < kk && above + g >= kk) {
                int acc = above, d = base + 7;
                for (; d >= base; d--) { int c = hist[d]; if (acc + c >= kk) break; acc += c; }
                s_prefix = pref | ((unsigned)d << shift);
                s_kk = kk - acc;
            }
        }
        __syncthreads();
    }
    unsigned kth = s_prefix;
    for (int s = tid; s < S_; s += 256) if (key[s] > kth) atomicAdd(&s_G, 1);
    __syncthreads();
    int limit = PATCHNUM - s_G;   // equals to admit, ascending index (lax.top_k tie order)
    for (int s = tid; s < S_; s += 256) {
        unsigned ky = key[s]; bool sel;
        if (ky > kth) sel = true;
        else if (ky == kth) { int er = 0; for (int j = 0; j < s; j++) er += (key[j] == kth); sel = (er < limit); }
        else sel = false;
        float v = sc[s];
        g_new[bc*S_ + s] = sel ? v : SCALE_ * v;
        g_sel[bc*S_ + s] = sel ? 1 : 0;
    }
}

// ---------------- warp-shuffle block sum ----------------
__device__ __forceinline__ float blockSum(float v, int tid, float* buf) {
    #pragma unroll
    for (int o = 16; o; o >>= 1) v += __shfl_down_sync(0xffffffffu, v, o);
    if ((tid & 31) == 0) buf[tid >> 5] = v;
    __syncthreads();
    if (tid < 8) {
        v = buf[tid];
        #pragma unroll
        for (int o = 4; o; o >>= 1) { float t = __shfl_down_sync(0xffu, v, o); if (tid + o < 8) v += t; }
        if (tid == 0) buf[0] = v;
    }
    __syncthreads();
    float r = buf[0];
    __syncthreads();
    return r;
}

// ---------------- Kernel B: per-batch stats ----------------
// grid 8 x 256
__global__ void kB(const float* __restrict__ w1) {
    int b = blockIdx.x, tid = threadIdx.x;
    __shared__ float sm[S_], scnt[S_];
    __shared__ float buf[32];
    __shared__ int bufi[8];

    for (int s = tid; s < S_; s += 256) {
        float acc = 0.0f; int cn = 0;
        #pragma unroll
        for (int c = 0; c < C_; c++) {
            acc += g_new[(b*C_ + c)*S_ + s];
            cn  += g_sel[(b*C_ + c)*S_ + s];
        }
        sm[s] = acc; scnt[s] = (float)cn;
    }
    __syncthreads();

    float p = 0.0f;
    for (int s = tid; s < S_; s += 256) p += sm[s];
    float mean = blockSum(p, tid, buf) * (1.0f / (float)S_);

    // argmax of binary*pw (first-index ties)
    float bv = -1e30f; int bi = S_;
    for (int s = tid; s < S_; s += 256) {
        float pw = sm[s] * (1.0f/12.0f);
        float v  = (sm[s] > mean) ? pw : 0.0f;
        if (v > bv || (v == bv && s < bi)) { bv = v; bi = s; }
    }
    #pragma unroll
    for (int o = 16; o; o >>= 1) {
        float v2 = __shfl_down_sync(0xffffffffu, bv, o);
        int   i2 = __shfl_down_sync(0xffffffffu, bi, o);
        if (v2 > bv || (v2 == bv && i2 < bi)) { bv = v2; bi = i2; }
    }
    if ((tid & 31) == 0) { buf[tid >> 5] = bv; bufi[tid >> 5] = bi; }
    __syncthreads();
    if (tid == 0) {
        bv = buf[0]; bi = bufi[0];
        for (int w = 1; w < 8; w++) {
            float v2 = buf[w]; int i2 = bufi[w];
            if (v2 > bv || (v2 == bv && i2 < bi)) { bv = v2; bi = i2; }
        }
        bufi[0] = bi;
    }
    __syncthreads();
    int anchor = bufi[0];
    __syncthreads();

    int ai = anchor / H_, aj = anchor % H_;
    const float INVPI = 0.318309886183790672f;
    float cd = 0.0f, ca = 0.0f, pp = 0.0f, pn = 0.0f;
    for (int s = tid; s < S_; s += 256) {
        float pw = sm[s] * (1.0f/12.0f);
        int ii = s / H_, jj = s % H_;
        float di = (float)(ii - ai) / (float)H_;
        float dj = (float)(jj - aj) / (float)H_;
        cd += pw * sqrtf(di*di + dj*dj);
        ca += pw * ((atan2f(dj, di) * INVPI + 1.0f) * 0.5f);
        float q = pw * pw;
        if (pw > 0.0f) pp += q; else if (pw < 0.0f) pn += q;
    }
    float CD = blockSum(cd, tid, buf);
    float CA = blockSum(ca, tid, buf);
    float PP = blockSum(pp, tid, buf);
    float PN = blockSum(pn, tid, buf);

    for (int k = tid; k < K_; k += 256) {
        float v1 = CD * w1[k] + CA * w1[K_ + k];
        g_u[b*K_ + k] = PP * fmaxf(v1, 0.0f) + PN * fminf(v1, 0.0f);
    }
    if (tid == 0) g_pa[b] = sm[anchor] * (1.0f/12.0f);

    // 3x3 conv of counts -> integer sort keys
    for (int s = tid; s < S_; s += 256) {
        int ii = s / H_, jj = s % H_;
        float acc = 0.0f;
        #pragma unroll
        for (int d2 = -1; d2 <= 1; d2++) {
            #pragma unroll
            for (int e2 = -1; e2 <= 1; e2++) {
                int i2 = ii + d2, j2 = jj + e2;
                if (i2 >= 0 && i2 < H_ && j2 >= 0 && j2 < H_)
                    acc += (float)((2 - abs(d2)) * (2 - abs(e2))) * scnt[i2*H_ + j2];
            }
        }
        int ic = (int)(acc + 0.5f);
        g_key[b*S_ + s] = (ic << 10) | (1023 - s);
    }
}

// ---------------- Kernel Mid: blocks 0..7 = count top-sn rank; 8..31 = batched matvec ----------------
__global__ void kMid(const float* __restrict__ w2, int sn) {
    __shared__ float su[B_*K_];        // 16KB (MV branch)
    __shared__ float red[2048];        // 8KB  (MV branch)
    __shared__ int sk[S_];             // rank branch
    __shared__ int hist[256];
    __shared__ unsigned s_prefix; __shared__ int s_kk;
    int tid = threadIdx.x;

    if (blockIdx.x < 8) {
        if (sn <= 0) return;
        int b = blockIdx.x;
        for (int s = tid; s < S_; s += 256) sk[s] = g_key[b*S_ + s];
        if (tid == 0) { s_prefix = 0u; s_kk = sn; }
        __syncthreads();
        // keys < 2^18, distinct -> 3 rounds of 8-bit radix select for sn-th largest
        for (int round = 0; round < 3; round++) {
            int shift = 16 - round * 8;
            hist[tid] = 0;
            __syncthreads();
            unsigned pref = s_prefix; int kk = s_kk;
            for (int s = tid; s < S_; s += 256) {
                unsigned ky = (unsigned)sk[s];
                if ((ky >> (shift + 8)) == (pref >> (shift + 8)))
                    atomicAdd(&hist[(ky >> shift) & 255], 1);
            }
            __syncthreads();
            if (tid < 32) {
                int base = tid * 8, g = 0;
                #pragma unroll
                for (int i = 0; i < 8; i++) g += hist[base + i];
                int a = g;
                #pragma unroll
                for (int o = 1; o < 32; o <<= 1) { int t = __shfl_down_sync(0xffffffffu, a, o); if (tid + o < 32) a += t; }
                int above = a - g;
                if (above < kk && above + g >= kk) {
                    int acc = above, d = base + 7;
                    for (; d >= base; d--) { int c = hist[d]; if (acc + c >= kk) break; acc += c; }
                    s_prefix = pref | ((unsigned)d << shift);
                    s_kk = kk - acc;
                }
            }
            __syncthreads();
        }
        unsigned T = s_prefix;   // sn-th largest key (keys distinct)
        for (int s = tid; s < S_; s += 256) {
            unsigned ky = (unsigned)sk[s];
            if (ky >= T) {
                int r = 0;
                for (int j = 0; j < S_; j++) r += ((unsigned)sk[j] > ky);
                if (r < sn) g_patch[b*64 + r] = s + 1;
            }
        }
    } else {
        // Batched matvec: each block owns 32 D-cols, reads W2 slab ONCE, reuses x8 batches.
        int d0 = (blockIdx.x - 8) * 32;
        int dl = tid & 31, kg = tid >> 5;   // 8 k-groups of 64
        for (int i = tid; i < B_*K_; i += 256) su[i] = g_u[i];
        __syncthreads();
        float acc[B_];
        #pragma unroll
        for (int b = 0; b < B_; b++) acc[b] = 0.0f;
        int kbase = kg * 64;
        #pragma unroll 4
        for (int kk = 0; kk < 64; kk++) {
            int k = kbase + kk;
            float w = w2[k*D_ + d0 + dl];
            #pragma unroll
            for (int b = 0; b < B_; b++) acc[b] += su[b*K_ + k] * w;
        }
        #pragma unroll
        for (int b = 0; b < B_; b++) red[kg*256 + b*32 + dl] = acc[b];
        __syncthreads();
        {
            int b = tid >> 5;
            float s = 0.0f;
            #pragma unroll
            for (int g2 = 0; g2 < 8; g2++) s += red[g2*256 + tid];
            float o = g_pa[b] * s;
            g_structA[b*D_ + d0 + dl] = (o > 0.0f) ? o : 0.2f * o;
        }
    }
}

// ---------------- Kernel Out: copy (+row0 add) and gather fused ----------------
__global__ void kOut(const float4* __restrict__ hid, float4* __restrict__ out,
                     int sn, int copyBlocks) {
    int blk = blockIdx.x;
    if (blk < copyBlocks) {
        int idx = blk * 256 + threadIdx.x;
        const int total = B_*N_*D_/4;
        if (idx >= total) return;
        float4 v = hid[idx];
        int f = idx * 4;
        int d = f % D_;
        int r = f / D_;
        int n = r % N_;
        if (n == 0) {
            int b = r / N_;
            const float4 sv = *(const float4*)&g_structA[b*D_ + d];
            v.x += sv.x; v.y += sv.y; v.z += sv.z; v.w += sv.w;
        }
        out[idx] = v;
    } else {
        int idx = (blk - copyBlocks) * 256 + threadIdx.x;
        int total = B_ * sn * (D_/4);
        if (idx >= total) return;
        int dl = idx % (D_/4);
        int qq = idx / (D_/4);
        int q  = qq % sn;
        int b  = qq / sn;
        int row = g_patch[b*64 + q];   // rows >= 1, untouched by row-0 add
        out[B_*N_*(D_/4) + idx] = hid[(b*N_ + row)*(D_/4) + dl];
    }
}

extern "C" void kernel_launch(void* const* d_in, const int* in_sizes, int n_in,
                              void* d_out, int out_size) {
    const float* hid = (const float*)d_in[0];
    const float* x   = (const float*)d_in[1];
    const float* w1  = (const float*)d_in[2];
    const float* w2  = (const float*)d_in[3];
    int sn = (out_size - B_*N_*D_) / (B_*D_);
    if (sn < 0)  sn = 0;
    if (sn > 64) sn = 64;

    kA<<<B_*C_, 256>>>(x);
    kB<<<B_, 256>>>(w1);
    kMid<<<32, 256>>>(w2, sn);
    int copyBlocks = (B_*N_*D_/4 + 255) / 256;
    int gatherBlocks = (B_*sn*(D_/4) + 255) / 256;
    kOut<<<copyBlocks + gatherBlocks, 256>>>((const float4*)hid, (float4*)d_out, sn, copyBlocks);
}